// round 12
// baseline (speedup 1.0000x reference)
#include <cuda_runtime.h>
#include <cstddef>
#include <cstdint>

// mRoPE, 256-bit global accesses (sm_103a).
// R10 L2 residency policy (stream=evict_first, cos/sin=evict_last)
// + R9 L1::evict_first on touch-once stream loads
// + 512-thread blocks (same 1 chunk/thread shape, half the CTAs).
// q[T, 32*128], k[T, 8*128], cos/sin[3, T, 64]; half = 64.
// sections (32,32,32): j<32 -> plane 0, j in [32,64) -> plane 1.
// out[j]    = x[j]*c[j]   - x[j+64]*s[j]
// out[j+64] = x[j+64]*c[j] + x[j]*s[j]

#define T_TOK 16384
#define HALF  64
#define NQH   32
#define NKH   8
#define HS    128

#define Q_CHUNKS (T_TOK * NQH * (HALF / 8))   // 4,194,304
#define K_CHUNKS (T_TOK * NKH * (HALF / 8))   // 1,048,576
#define TPB      512
#define Q_BLOCKS (Q_CHUNKS / TPB)             // 8192
#define K_BLOCKS (K_CHUNKS / TPB)             // 2048

struct V8 { uint32_t r[8]; };

__device__ __forceinline__ uint64_t make_policy_evict_first()
{
    uint64_t pol;
    asm("createpolicy.fractional.L2::evict_first.b64 %0, 1.0;" : "=l"(pol));
    return pol;
}

__device__ __forceinline__ uint64_t make_policy_evict_last()
{
    uint64_t pol;
    asm("createpolicy.fractional.L2::evict_last.b64 %0, 1.0;" : "=l"(pol));
    return pol;
}

// Touch-once stream load: L1 evict-first + L2 evict-first.
__device__ __forceinline__ V8 ldg256_stream(const float* p, uint64_t pol)
{
    V8 v;
    asm volatile("ld.global.nc.L1::evict_first.L2::cache_hint.v8.b32 "
                 "{%0,%1,%2,%3,%4,%5,%6,%7}, [%8], %9;"
                 : "=r"(v.r[0]), "=r"(v.r[1]), "=r"(v.r[2]), "=r"(v.r[3]),
                   "=r"(v.r[4]), "=r"(v.r[5]), "=r"(v.r[6]), "=r"(v.r[7])
                 : "l"(p), "l"(pol));
    return v;
}

// Reused cos/sin load: default L1, L2 evict-last (pin across replays).
__device__ __forceinline__ V8 ldg256_pin(const float* p, uint64_t pol)
{
    V8 v;
    asm volatile("ld.global.nc.L2::cache_hint.v8.b32 "
                 "{%0,%1,%2,%3,%4,%5,%6,%7}, [%8], %9;"
                 : "=r"(v.r[0]), "=r"(v.r[1]), "=r"(v.r[2]), "=r"(v.r[3]),
                   "=r"(v.r[4]), "=r"(v.r[5]), "=r"(v.r[6]), "=r"(v.r[7])
                 : "l"(p), "l"(pol));
    return v;
}

// Stream store: L2 evict-first (writeback path, don't displace cos/sin).
__device__ __forceinline__ void stg256(float* p, const V8& v, uint64_t pol)
{
    asm volatile("st.global.L2::cache_hint.v8.b32 [%0], {%1,%2,%3,%4,%5,%6,%7,%8}, %9;"
                 :: "l"(p),
                    "r"(v.r[0]), "r"(v.r[1]), "r"(v.r[2]), "r"(v.r[3]),
                    "r"(v.r[4]), "r"(v.r[5]), "r"(v.r[6]), "r"(v.r[7]),
                    "l"(pol)
                 : "memory");
}

__device__ __forceinline__ void rope_chunk(const float* __restrict__ src,
                                           float* __restrict__ dst,
                                           const float* __restrict__ cosp,
                                           const float* __restrict__ sinp,
                                           size_t off, size_t cs_off,
                                           uint64_t pol_stream, uint64_t pol_pin)
{
    const V8 a = ldg256_stream(src + off,        pol_stream);  // x1
    const V8 b = ldg256_stream(src + off + HALF, pol_stream);  // x2
    const V8 c = ldg256_pin(cosp + cs_off, pol_pin);
    const V8 s = ldg256_pin(sinp + cs_off, pol_pin);

    V8 o1, o2;
#pragma unroll
    for (int e = 0; e < 8; e++) {
        const float af = __uint_as_float(a.r[e]);
        const float bf = __uint_as_float(b.r[e]);
        const float cf = __uint_as_float(c.r[e]);
        const float sf = __uint_as_float(s.r[e]);
        o1.r[e] = __float_as_uint(fmaf(af, cf, -bf * sf));
        o2.r[e] = __float_as_uint(fmaf(bf, cf,  af * sf));
    }

    stg256(dst + off,        o1, pol_stream);
    stg256(dst + off + HALF, o2, pol_stream);
}

__global__ __launch_bounds__(TPB)
void mrope_v8l2b_kernel(const float* __restrict__ q,
                        const float* __restrict__ k,
                        const float* __restrict__ cosp,
                        const float* __restrict__ sinp,
                        float* __restrict__ qo,
                        float* __restrict__ ko)
{
    const int bid = blockIdx.x;
    const int tid = threadIdx.x;

    const uint64_t pol_stream = make_policy_evict_first();
    const uint64_t pol_pin    = make_policy_evict_last();

    if (bid < Q_BLOCKS) {
        const int i  = bid * TPB + tid;    // q chunk index
        const int t  = i >> 8;             // 256 chunks/token
        const int r  = i & 255;
        const int j8 = r & 7;              // chunk within half (0..7)
        const size_t off    = ((size_t)t << 12) + ((size_t)(r >> 3) << 7) + (j8 << 3);
        const size_t cs_off = (size_t)(j8 >> 2) * (T_TOK * HALF) + ((size_t)t << 6) + (j8 << 3);
        rope_chunk(q, qo, cosp, sinp, off, cs_off, pol_stream, pol_pin);
    } else {
        const int i  = (bid - Q_BLOCKS) * TPB + tid;  // k chunk index
        const int t  = i >> 6;             // 64 chunks/token
        const int r  = i & 63;
        const int j8 = r & 7;
        const size_t off    = ((size_t)t << 10) + ((size_t)(r >> 3) << 7) + (j8 << 3);
        const size_t cs_off = (size_t)(j8 >> 2) * (T_TOK * HALF) + ((size_t)t << 6) + (j8 << 3);
        rope_chunk(k, ko, cosp, sinp, off, cs_off, pol_stream, pol_pin);
    }
}

extern "C" void kernel_launch(void* const* d_in, const int* in_sizes, int n_in,
                              void* d_out, int out_size)
{
    const float* q    = (const float*)d_in[0];
    const float* k    = (const float*)d_in[1];
    const float* cosp = (const float*)d_in[2];
    const float* sinp = (const float*)d_in[3];

    float* qo = (float*)d_out;
    float* ko = qo + (size_t)T_TOK * NQH * HS;

    mrope_v8l2b_kernel<<<Q_BLOCKS + K_BLOCKS, TPB>>>(q, k, cosp, sinp, qo, ko);
}

// round 17
// speedup vs baseline: 1.0016x; 1.0016x over previous
#include <cuda_runtime.h>
#include <cstddef>
#include <cstdint>

// mRoPE, 256-bit global accesses (sm_103a). Final form (R10 + pin-loads-first):
//   q/k loads  -> L2::evict_first  (touch-once stream)
//   cos/sin    -> L2::evict_last   (pin ~17MB table across graph replays)
//   stores     -> L2::evict_first  (writeback path, don't displace cos/sin)
//   cos/sin loads issued first (L2 hits land early; stream loads cover latency)
// q[T, 32*128], k[T, 8*128], cos/sin[3, T, 64]; half = 64.
// sections (32,32,32): j<32 -> plane 0, j in [32,64) -> plane 1.
// out[j]    = x[j]*c[j]   - x[j+64]*s[j]
// out[j+64] = x[j+64]*c[j] + x[j]*s[j]

#define T_TOK 16384
#define HALF  64
#define NQH   32
#define NKH   8
#define HS    128

#define Q_CHUNKS (T_TOK * NQH * (HALF / 8))   // 4,194,304
#define K_CHUNKS (T_TOK * NKH * (HALF / 8))   // 1,048,576
#define Q_BLOCKS (Q_CHUNKS / 256)             // 16384
#define K_BLOCKS (K_CHUNKS / 256)             // 4096

struct V8 { uint32_t r[8]; };

__device__ __forceinline__ uint64_t make_policy_evict_first()
{
    uint64_t pol;
    asm("createpolicy.fractional.L2::evict_first.b64 %0, 1.0;" : "=l"(pol));
    return pol;
}

__device__ __forceinline__ uint64_t make_policy_evict_last()
{
    uint64_t pol;
    asm("createpolicy.fractional.L2::evict_last.b64 %0, 1.0;" : "=l"(pol));
    return pol;
}

// Touch-once stream load: L2 evict-first.
__device__ __forceinline__ V8 ldg256_stream(const float* p, uint64_t pol)
{
    V8 v;
    asm volatile("ld.global.nc.L2::cache_hint.v8.b32 {%0,%1,%2,%3,%4,%5,%6,%7}, [%8], %9;"
                 : "=r"(v.r[0]), "=r"(v.r[1]), "=r"(v.r[2]), "=r"(v.r[3]),
                   "=r"(v.r[4]), "=r"(v.r[5]), "=r"(v.r[6]), "=r"(v.r[7])
                 : "l"(p), "l"(pol));
    return v;
}

// Reused cos/sin load: L2 evict-last (pin across replays).
__device__ __forceinline__ V8 ldg256_pin(const float* p, uint64_t pol)
{
    V8 v;
    asm volatile("ld.global.nc.L2::cache_hint.v8.b32 {%0,%1,%2,%3,%4,%5,%6,%7}, [%8], %9;"
                 : "=r"(v.r[0]), "=r"(v.r[1]), "=r"(v.r[2]), "=r"(v.r[3]),
                   "=r"(v.r[4]), "=r"(v.r[5]), "=r"(v.r[6]), "=r"(v.r[7])
                 : "l"(p), "l"(pol));
    return v;
}

// Stream store: L2 evict-first (writeback, don't displace cos/sin).
__device__ __forceinline__ void stg256(float* p, const V8& v, uint64_t pol)
{
    asm volatile("st.global.L2::cache_hint.v8.b32 [%0], {%1,%2,%3,%4,%5,%6,%7,%8}, %9;"
                 :: "l"(p),
                    "r"(v.r[0]), "r"(v.r[1]), "r"(v.r[2]), "r"(v.r[3]),
                    "r"(v.r[4]), "r"(v.r[5]), "r"(v.r[6]), "r"(v.r[7]),
                    "l"(pol)
                 : "memory");
}

__device__ __forceinline__ void rope_chunk(const float* __restrict__ src,
                                           float* __restrict__ dst,
                                           const float* __restrict__ cosp,
                                           const float* __restrict__ sinp,
                                           size_t off, size_t cs_off,
                                           uint64_t pol_stream, uint64_t pol_pin)
{
    // Pinned (likely L2-hit) loads first; DRAM-latency stream loads overlap.
    const V8 c = ldg256_pin(cosp + cs_off, pol_pin);
    const V8 s = ldg256_pin(sinp + cs_off, pol_pin);
    const V8 a = ldg256_stream(src + off,        pol_stream);  // x1
    const V8 b = ldg256_stream(src + off + HALF, pol_stream);  // x2

    V8 o1, o2;
#pragma unroll
    for (int e = 0; e < 8; e++) {
        const float af = __uint_as_float(a.r[e]);
        const float bf = __uint_as_float(b.r[e]);
        const float cf = __uint_as_float(c.r[e]);
        const float sf = __uint_as_float(s.r[e]);
        o1.r[e] = __float_as_uint(fmaf(af, cf, -bf * sf));
        o2.r[e] = __float_as_uint(fmaf(bf, cf,  af * sf));
    }

    stg256(dst + off,        o1, pol_stream);
    stg256(dst + off + HALF, o2, pol_stream);
}

__global__ __launch_bounds__(256)
void mrope_v8fin_kernel(const float* __restrict__ q,
                        const float* __restrict__ k,
                        const float* __restrict__ cosp,
                        const float* __restrict__ sinp,
                        float* __restrict__ qo,
                        float* __restrict__ ko)
{
    const int bid = blockIdx.x;
    const int tid = threadIdx.x;

    const uint64_t pol_stream = make_policy_evict_first();
    const uint64_t pol_pin    = make_policy_evict_last();

    if (bid < Q_BLOCKS) {
        const int i  = (bid << 8) + tid;   // q chunk index
        const int t  = i >> 8;             // 256 chunks/token
        const int r  = i & 255;
        const int j8 = r & 7;              // chunk within half (0..7)
        const size_t off    = ((size_t)t << 12) + ((size_t)(r >> 3) << 7) + (j8 << 3);
        const size_t cs_off = (size_t)(j8 >> 2) * (T_TOK * HALF) + ((size_t)t << 6) + (j8 << 3);
        rope_chunk(q, qo, cosp, sinp, off, cs_off, pol_stream, pol_pin);
    } else {
        const int i  = ((bid - Q_BLOCKS) << 8) + tid;  // k chunk index
        const int t  = i >> 6;             // 64 chunks/token
        const int r  = i & 63;
        const int j8 = r & 7;
        const size_t off    = ((size_t)t << 10) + ((size_t)(r >> 3) << 7) + (j8 << 3);
        const size_t cs_off = (size_t)(j8 >> 2) * (T_TOK * HALF) + ((size_t)t << 6) + (j8 << 3);
        rope_chunk(k, ko, cosp, sinp, off, cs_off, pol_stream, pol_pin);
    }
}

extern "C" void kernel_launch(void* const* d_in, const int* in_sizes, int n_in,
                              void* d_out, int out_size)
{
    const float* q    = (const float*)d_in[0];
    const float* k    = (const float*)d_in[1];
    const float* cosp = (const float*)d_in[2];
    const float* sinp = (const float*)d_in[3];

    float* qo = (float*)d_out;
    float* ko = qo + (size_t)T_TOK * NQH * HS;

    mrope_v8fin_kernel<<<Q_BLOCKS + K_BLOCKS, 256>>>(q, k, cosp, sinp, qo, ko);
}